// round 1
// baseline (speedup 1.0000x reference)
#include <cuda_runtime.h>
#include <math.h>

// ---------------- scratch (static device globals; no allocation) ----------------
__device__ float g_h1[8*256*64*64];   // after conv1, 64x64
__device__ float g_h2[8*256*32*32];   // encoder trunk, 32x32
__device__ float g_r3[8*256*32*32];   // residual branch 3x3 output
__device__ float g_d1[8*256*32*32];   // decoder after from_z
__device__ float g_d2[8*256*64*64];   // decoder after t1
__device__ float g_csq[512];
__device__ int   g_ids[8192];

// ---------------- conv1: 3->256, k4 s2 p1, 128->64, ReLU ----------------
__global__ __launch_bounds__(256) void conv1_k(const float* __restrict__ x,
                                               const float* __restrict__ w,
                                               const float* __restrict__ bias){
    int co = blockIdx.x, b = blockIdx.y;
    __shared__ float sw[48];
    if (threadIdx.x < 48) sw[threadIdx.x] = w[co*48 + threadIdx.x];
    __syncthreads();
    float bb = bias[co];
    const float* xb = x + (size_t)b*3*128*128;
    float* outp = g_h1 + ((size_t)(b*256 + co))*4096;
    for (int p = threadIdx.x; p < 4096; p += 256){
        int oy = p >> 6, ox = p & 63;
        float acc = bb;
        #pragma unroll
        for (int ci = 0; ci < 3; ci++){
            #pragma unroll
            for (int ky = 0; ky < 4; ky++){
                int iy = 2*oy - 1 + ky;
                if ((unsigned)iy < 128u){
                    #pragma unroll
                    for (int kx = 0; kx < 4; kx++){
                        int ix = 2*ox - 1 + kx;
                        if ((unsigned)ix < 128u)
                            acc = fmaf(sw[(ci*4+ky)*4+kx], __ldg(&xb[(ci*128+iy)*128+ix]), acc);
                    }
                }
            }
        }
        outp[p] = fmaxf(acc, 0.f);
    }
}

// ---------------- conv2: 256->256, k4 s2 p1, 64->32, ReLU ----------------
// grid (4 pxtile, 16 cotile, 8 b), block 256. Tile: 16 co x 16x16 px. 4co x 4px per thread.
__global__ __launch_bounds__(256) void conv2_k(const float* __restrict__ w,
                                               const float* __restrict__ bias){
    int b = blockIdx.z;
    int co0 = blockIdx.y * 16;
    int oy0 = (blockIdx.x >> 1) * 16, ox0 = (blockIdx.x & 1) * 16;
    __shared__ float s_w[4][16][16];     // [ci][tap][co]
    __shared__ float s_in[4][34][34];
    int tid = threadIdx.x;
    int co_g = tid >> 6;        // 0..3
    int pg = tid & 63;
    int ly = pg >> 2;           // 0..15
    int lx0 = (pg & 3) * 4;     // 0,4,8,12
    float acc[4][4] = {};
    const float* inb = g_h1 + (size_t)b*256*4096;
    int iy_base = 2*oy0 - 1, ix_base = 2*ox0 - 1;
    for (int c0 = 0; c0 < 256; c0 += 4){
        for (int i = tid; i < 1024; i += 256){
            int ci = i >> 8, tap = (i >> 4) & 15, col = i & 15;
            s_w[ci][tap][col] = w[(size_t)((co0+col)*256 + c0+ci)*16 + tap];
        }
        for (int i = tid; i < 4624; i += 256){
            int ci = i / 1156, rem = i % 1156;
            int yy = rem / 34, xx = rem % 34;
            int iy = iy_base + yy, ix = ix_base + xx;
            float v = 0.f;
            if ((unsigned)iy < 64u && (unsigned)ix < 64u)
                v = inb[(size_t)((c0+ci)*64 + iy)*64 + ix];
            s_in[ci][yy][xx] = v;
        }
        __syncthreads();
        #pragma unroll
        for (int ci = 0; ci < 4; ci++){
            #pragma unroll
            for (int ky = 0; ky < 4; ky++){
                #pragma unroll
                for (int kx = 0; kx < 4; kx++){
                    int tap = ky*4 + kx;
                    float w0 = s_w[ci][tap][co_g*4+0];
                    float w1 = s_w[ci][tap][co_g*4+1];
                    float w2 = s_w[ci][tap][co_g*4+2];
                    float w3 = s_w[ci][tap][co_g*4+3];
                    int ry = 2*ly + ky;
                    #pragma unroll
                    for (int j = 0; j < 4; j++){
                        float iv = s_in[ci][ry][2*(lx0+j)+kx];
                        acc[0][j] = fmaf(w0, iv, acc[0][j]);
                        acc[1][j] = fmaf(w1, iv, acc[1][j]);
                        acc[2][j] = fmaf(w2, iv, acc[2][j]);
                        acc[3][j] = fmaf(w3, iv, acc[3][j]);
                    }
                }
            }
        }
        __syncthreads();
    }
    int oy = oy0 + ly;
    #pragma unroll
    for (int i = 0; i < 4; i++){
        int co = co0 + co_g*4 + i;
        float bb = bias[co];
        #pragma unroll
        for (int j = 0; j < 4; j++){
            int ox = ox0 + lx0 + j;
            g_h2[(size_t)((b*256+co)*32 + oy)*32 + ox] = fmaxf(acc[i][j] + bb, 0.f);
        }
    }
}

// ---------------- conv3x3 pad1 (res branch): relu(in) -> g_r3 (+bias) ----------------
__global__ __launch_bounds__(256) void conv3_k(const float* __restrict__ w,
                                               const float* __restrict__ bias){
    int b = blockIdx.z;
    int co0 = blockIdx.y * 16;
    int oy0 = (blockIdx.x >> 1) * 16, ox0 = (blockIdx.x & 1) * 16;
    __shared__ float s_w[4][9][16];      // [ci][tap][co]
    __shared__ float s_in[4][18][18];
    int tid = threadIdx.x;
    int co_g = tid >> 6;
    int pg = tid & 63;
    int ly = pg >> 2;
    int lx0 = (pg & 3) * 4;
    float acc[4][4] = {};
    const float* inb = g_h2 + (size_t)b*256*1024;
    for (int c0 = 0; c0 < 256; c0 += 4){
        for (int i = tid; i < 576; i += 256){
            int ci = i / 144, rem = i % 144;
            int tap = rem / 16, col = rem % 16;
            s_w[ci][tap][col] = w[(size_t)((co0+col)*256 + c0+ci)*9 + tap];
        }
        for (int i = tid; i < 1296; i += 256){
            int ci = i / 324, rem = i % 324;
            int yy = rem / 18, xx = rem % 18;
            int iy = oy0 - 1 + yy, ix = ox0 - 1 + xx;
            float v = 0.f;
            if ((unsigned)iy < 32u && (unsigned)ix < 32u)
                v = fmaxf(inb[(size_t)((c0+ci)*32 + iy)*32 + ix], 0.f);
            s_in[ci][yy][xx] = v;
        }
        __syncthreads();
        #pragma unroll
        for (int ci = 0; ci < 4; ci++){
            #pragma unroll
            for (int ky = 0; ky < 3; ky++){
                #pragma unroll
                for (int kx = 0; kx < 3; kx++){
                    int tap = ky*3 + kx;
                    float w0 = s_w[ci][tap][co_g*4+0];
                    float w1 = s_w[ci][tap][co_g*4+1];
                    float w2 = s_w[ci][tap][co_g*4+2];
                    float w3 = s_w[ci][tap][co_g*4+3];
                    int ry = ly + ky;
                    #pragma unroll
                    for (int j = 0; j < 4; j++){
                        float iv = s_in[ci][ry][lx0 + j + kx];
                        acc[0][j] = fmaf(w0, iv, acc[0][j]);
                        acc[1][j] = fmaf(w1, iv, acc[1][j]);
                        acc[2][j] = fmaf(w2, iv, acc[2][j]);
                        acc[3][j] = fmaf(w3, iv, acc[3][j]);
                    }
                }
            }
        }
        __syncthreads();
    }
    int oy = oy0 + ly;
    #pragma unroll
    for (int i = 0; i < 4; i++){
        int co = co0 + co_g*4 + i;
        float bb = bias[co];
        #pragma unroll
        for (int j = 0; j < 4; j++){
            int ox = ox0 + lx0 + j;
            g_r3[(size_t)((b*256+co)*32 + oy)*32 + ox] = acc[i][j] + bb;
        }
    }
}

// ---------------- conv1x1 GEMM (generic) ----------------
// grid (8 pxtiles of 128, Cout/32, 8 b), block 256: 8 co groups x 32 px groups, 4co x 4px per thread.
template<int CIN, bool RELU_IN, bool RELU_OUT, bool ADD_RES>
__global__ __launch_bounds__(256) void conv1x1_k(const float* __restrict__ in,
                                                 const float* __restrict__ w,
                                                 const float* __restrict__ bias,
                                                 const float* res, float* out){
    int b = blockIdx.z;
    int co0 = blockIdx.y * 32;
    int p0 = blockIdx.x * 128;
    int COUT = gridDim.y * 32;
    __shared__ float s_w[8][32];
    __shared__ float s_in[8][128];
    int tid = threadIdx.x;
    int co_g = tid >> 5;   // 0..7
    int px_g = tid & 31;   // 0..31
    float acc[4][4] = {};
    for (int c0 = 0; c0 < CIN; c0 += 8){
        {
            int ci = tid >> 5, col = tid & 31;
            s_w[ci][col] = w[(size_t)(co0+col)*CIN + c0 + ci];
        }
        for (int i = tid; i < 1024; i += 256){
            int ci = i >> 7, pp = i & 127;
            float v = in[(size_t)(b*CIN + c0+ci)*1024 + p0 + pp];
            if (RELU_IN) v = fmaxf(v, 0.f);
            s_in[ci][pp] = v;
        }
        __syncthreads();
        #pragma unroll
        for (int ci = 0; ci < 8; ci++){
            float4 wv = *reinterpret_cast<const float4*>(&s_w[ci][co_g*4]);
            float4 iv = *reinterpret_cast<const float4*>(&s_in[ci][px_g*4]);
            float wr[4] = {wv.x, wv.y, wv.z, wv.w};
            float ir[4] = {iv.x, iv.y, iv.z, iv.w};
            #pragma unroll
            for (int i = 0; i < 4; i++)
                #pragma unroll
                for (int j = 0; j < 4; j++)
                    acc[i][j] = fmaf(wr[i], ir[j], acc[i][j]);
        }
        __syncthreads();
    }
    #pragma unroll
    for (int i = 0; i < 4; i++){
        int co = co0 + co_g*4 + i;
        float bb = bias[co];
        #pragma unroll
        for (int j = 0; j < 4; j++){
            int p = p0 + px_g*4 + j;
            size_t idx = (size_t)(b*COUT + co)*1024 + p;
            float v = acc[i][j] + bb;
            if (ADD_RES) v += res[idx];
            if (RELU_OUT) v = fmaxf(v, 0.f);
            out[idx] = v;
        }
    }
}

// ---------------- VQ ----------------
__global__ void csq_k(const float* __restrict__ cb){
    int k = blockIdx.x*blockDim.x + threadIdx.x;
    if (k < 512){
        float s = 0.f;
        #pragma unroll
        for (int c = 0; c < 64; c++){ float v = cb[k*64+c]; s += v*v; }
        g_csq[k] = s;
    }
}

// block: 256 threads = 8 warps; block handles 32 vectors (one per lane);
// warp w scans codes [64w, 64w+64). z in registers, codebook loads warp-uniform (broadcast).
__global__ __launch_bounds__(256) void vq_k(const float* __restrict__ ze,
                                            const float* __restrict__ cb,
                                            float* __restrict__ ids_out){
    int warp = threadIdx.x >> 5, lane = threadIdx.x & 31;
    int n = blockIdx.x * 32 + lane;
    int b = n >> 10, p = n & 1023;
    const float* zb = ze + (size_t)b*65536 + p;
    float z[64];
    #pragma unroll
    for (int c = 0; c < 64; c++) z[c] = zb[(size_t)c*1024];
    float zz = 0.f;
    #pragma unroll
    for (int c = 0; c < 64; c++) zz += z[c]*z[c];
    float best = INFINITY; int bk = 0;
    int k0 = warp * 64;
    for (int kk = 0; kk < 64; kk++){
        int k = k0 + kk;
        const float* cp = cb + (size_t)k*64;
        float dot = 0.f;
        #pragma unroll
        for (int c = 0; c < 64; c++) dot = fmaf(z[c], __ldg(&cp[c]), dot);
        float d = (zz - 2.0f*dot) + g_csq[k];
        if (d < best){ best = d; bk = k; }
    }
    __shared__ float sv[8][32];
    __shared__ int   si[8][32];
    sv[warp][lane] = best; si[warp][lane] = bk;
    __syncthreads();
    if (warp == 0){
        float bv = sv[0][lane]; int bi = si[0][lane];
        #pragma unroll
        for (int w = 1; w < 8; w++){
            float v = sv[w][lane];
            if (v < bv){ bv = v; bi = si[w][lane]; }
        }
        g_ids[n] = bi;
        ids_out[n] = (float)bi;
    }
}

__global__ void ek_k(const float* __restrict__ cb, float* __restrict__ ek){
    int i = blockIdx.x*256 + threadIdx.x;
    if (i >= 8*64*1024) return;
    int b = i >> 16;
    int c = (i >> 10) & 63;
    int p = i & 1023;
    ek[i] = cb[(size_t)g_ids[(b<<10)|p]*64 + c];
}

// ---------------- t1: ConvTranspose 256->256, k4 s2 p1, 32->64, ReLU ----------------
// grid (16 pxtile, 16 cotile, 8 b), block 256. Tile 16co x 16x16 px.
__global__ __launch_bounds__(256) void t1_k(const float* __restrict__ w,
                                            const float* __restrict__ bias){
    int b = blockIdx.z;
    int co0 = blockIdx.y * 16;
    int oy0 = (blockIdx.x >> 2) * 16, ox0 = (blockIdx.x & 3) * 16;
    __shared__ float s_w[4][16][16];   // [ci][tap][co]
    __shared__ float s_in[4][10][10];
    int tid = threadIdx.x;
    int co_g = tid >> 6;
    int pg = tid & 63;
    int ly = pg >> 2;
    int lx0 = (pg & 3) * 4;
    float acc[4][4] = {};
    const float* inb = g_d1 + (size_t)b*256*1024;
    int iy0 = (oy0 >> 1) - 1, ix0 = (ox0 >> 1) - 1;
    int oy = oy0 + ly;
    int kyb = (oy + 1) & 1;
    for (int c0 = 0; c0 < 256; c0 += 4){
        for (int i = tid; i < 1024; i += 256){
            int ci = i >> 8, tap = (i >> 4) & 15, col = i & 15;
            s_w[ci][tap][col] = w[(size_t)((c0+ci)*256 + co0+col)*16 + tap];
        }
        for (int i = tid; i < 400; i += 256){
            int ci = i / 100, rem = i % 100;
            int yy = rem / 10, xx = rem % 10;
            int iy = iy0 + yy, ix = ix0 + xx;
            float v = 0.f;
            if ((unsigned)iy < 32u && (unsigned)ix < 32u)
                v = inb[(size_t)((c0+ci)*32 + iy)*32 + ix];
            s_in[ci][yy][xx] = v;
        }
        __syncthreads();
        #pragma unroll
        for (int ci = 0; ci < 4; ci++){
            #pragma unroll
            for (int kyi = 0; kyi < 2; kyi++){
                int ky = kyb + 2*kyi;
                int ryl = ((oy + 1 - ky) >> 1) - iy0;   // in [0,9], OOB rows were zero-filled
                #pragma unroll
                for (int kxi = 0; kxi < 2; kxi++){
                    #pragma unroll
                    for (int j = 0; j < 4; j++){
                        int ox = ox0 + lx0 + j;
                        int kx = ((ox + 1) & 1) + 2*kxi;
                        int rxl = ((ox + 1 - kx) >> 1) - ix0;
                        float iv = s_in[ci][ryl][rxl];
                        int tap = ky*4 + kx;
                        acc[0][j] = fmaf(s_w[ci][tap][co_g*4+0], iv, acc[0][j]);
                        acc[1][j] = fmaf(s_w[ci][tap][co_g*4+1], iv, acc[1][j]);
                        acc[2][j] = fmaf(s_w[ci][tap][co_g*4+2], iv, acc[2][j]);
                        acc[3][j] = fmaf(s_w[ci][tap][co_g*4+3], iv, acc[3][j]);
                    }
                }
            }
        }
        __syncthreads();
    }
    #pragma unroll
    for (int i = 0; i < 4; i++){
        int co = co0 + co_g*4 + i;
        float bb = bias[co];
        #pragma unroll
        for (int j = 0; j < 4; j++){
            int ox = ox0 + lx0 + j;
            g_d2[(size_t)((b*256+co)*64 + oy)*64 + ox] = fmaxf(acc[i][j] + bb, 0.f);
        }
    }
}

// ---------------- t2: ConvTranspose 256->3, k4 s2 p1, 64->128, sigmoid ----------------
// grid (64 row-pairs, 8 b), block 256 (2 rows x 128 ox).
__global__ __launch_bounds__(256) void t2_k(const float* __restrict__ w,
                                            const float* __restrict__ bias,
                                            float* __restrict__ out){
    int b = blockIdx.y;
    int r = blockIdx.x;
    int tid = threadIdx.x;
    int sub = tid >> 7;
    int ox = tid & 127;
    int oy = 2*r + sub;
    __shared__ float s_w[32][3][16];
    __shared__ float s_in[32][3][64];
    float acc[3] = {0.f, 0.f, 0.f};
    const float* inb = g_d2 + (size_t)b*256*4096;
    for (int c0 = 0; c0 < 256; c0 += 32){
        for (int i = tid; i < 1536; i += 256){
            int ci = i / 48, rem = i % 48;
            int co = rem / 16, tap = rem % 16;
            s_w[ci][co][tap] = w[(size_t)((c0+ci)*3 + co)*16 + tap];
        }
        for (int i = tid; i < 6144; i += 256){
            int ci = i / 192, rem = i % 192;
            int ryl = rem / 64, ix = rem % 64;
            int iy = r - 1 + ryl;
            float v = 0.f;
            if ((unsigned)iy < 64u)
                v = inb[(size_t)((c0+ci)*64 + iy)*64 + ix];
            s_in[ci][ryl][ix] = v;
        }
        __syncthreads();
        int kyb = (oy + 1) & 1;
        int kxb = (ox + 1) & 1;
        #pragma unroll 4
        for (int ci = 0; ci < 32; ci++){
            #pragma unroll
            for (int kyi = 0; kyi < 2; kyi++){
                int ky = kyb + 2*kyi;
                int ryl = ((oy + 1 - ky) >> 1) - (r - 1);
                #pragma unroll
                for (int kxi = 0; kxi < 2; kxi++){
                    int kx = kxb + 2*kxi;
                    int ix = (ox + 1 - kx) >> 1;
                    if ((unsigned)ix < 64u){
                        float iv = s_in[ci][ryl][ix];
                        int tap = ky*4 + kx;
                        acc[0] = fmaf(s_w[ci][0][tap], iv, acc[0]);
                        acc[1] = fmaf(s_w[ci][1][tap], iv, acc[1]);
                        acc[2] = fmaf(s_w[ci][2][tap], iv, acc[2]);
                    }
                }
            }
        }
        __syncthreads();
    }
    #pragma unroll
    for (int co = 0; co < 3; co++){
        float v = acc[co] + bias[co];
        out[(size_t)((b*3+co)*128 + oy)*128 + ox] = 1.f/(1.f + expf(-v));
    }
}

// ---------------- launch ----------------
extern "C" void kernel_launch(void* const* d_in, const int* in_sizes, int n_in,
                              void* d_out, int out_size){
    const float* x        = (const float*)d_in[0];
    const float* c1_w     = (const float*)d_in[1];
    const float* c1_b     = (const float*)d_in[2];
    const float* c2_w     = (const float*)d_in[3];
    const float* c2_b     = (const float*)d_in[4];
    const float* r0_w3    = (const float*)d_in[5];
    const float* r0_b3    = (const float*)d_in[6];
    const float* r0_w1    = (const float*)d_in[7];
    const float* r0_b1    = (const float*)d_in[8];
    const float* r1_w3    = (const float*)d_in[9];
    const float* r1_b3    = (const float*)d_in[10];
    const float* r1_w1    = (const float*)d_in[11];
    const float* r1_b1    = (const float*)d_in[12];
    const float* to_z_w   = (const float*)d_in[13];
    const float* to_z_b   = (const float*)d_in[14];
    const float* codebook = (const float*)d_in[15];
    const float* from_z_w = (const float*)d_in[16];
    const float* from_z_b = (const float*)d_in[17];
    const float* t1_w     = (const float*)d_in[18];
    const float* t1_b     = (const float*)d_in[19];
    const float* t2_w     = (const float*)d_in[20];
    const float* t2_b     = (const float*)d_in[21];

    float* outf = (float*)d_out;
    float* ze   = outf + 393216;            // 8*64*32*32
    float* ek   = outf + 917504;            // + 8*64*32*32
    float* idsf = outf + 1441792;           // + 8192

    float *p_h2 = 0, *p_r3 = 0, *p_d1 = 0;
    cudaGetSymbolAddress((void**)&p_h2, g_h2);
    cudaGetSymbolAddress((void**)&p_r3, g_r3);
    cudaGetSymbolAddress((void**)&p_d1, g_d1);

    // encoder
    conv1_k<<<dim3(256,8), 256>>>(x, c1_w, c1_b);
    conv2_k<<<dim3(4,16,8), 256>>>(c2_w, c2_b);
    // residual block 0
    conv3_k<<<dim3(4,16,8), 256>>>(r0_w3, r0_b3);
    conv1x1_k<256,true,false,true><<<dim3(8,8,8), 256>>>(p_r3, r0_w1, r0_b1, p_h2, p_h2);
    // residual block 1
    conv3_k<<<dim3(4,16,8), 256>>>(r1_w3, r1_b3);
    conv1x1_k<256,true,false,true><<<dim3(8,8,8), 256>>>(p_r3, r1_w1, r1_b1, p_h2, p_h2);
    // to_z -> z_e (output)
    conv1x1_k<256,false,false,false><<<dim3(8,2,8), 256>>>(p_h2, to_z_w, to_z_b, nullptr, ze);
    // VQ
    csq_k<<<2,256>>>(codebook);
    vq_k<<<256,256>>>(ze, codebook, idsf);
    ek_k<<<2048,256>>>(codebook, ek);
    // decoder
    conv1x1_k<64,false,true,false><<<dim3(8,8,8), 256>>>(ek, from_z_w, from_z_b, nullptr, p_d1);
    t1_k<<<dim3(16,16,8), 256>>>(t1_w, t1_b);
    t2_k<<<dim3(64,8), 256>>>(t2_w, t2_b, outf);
}

// round 2
// speedup vs baseline: 1.1545x; 1.1545x over previous
#include <cuda_runtime.h>
#include <math.h>

typedef unsigned long long u64;

__device__ __forceinline__ void ffma2(u64 &acc, u64 a, u64 b){
    asm("fma.rn.f32x2 %0, %1, %2, %0;" : "+l"(acc) : "l"(a), "l"(b));
}
__device__ __forceinline__ u64 pack2(float lo, float hi){
    u64 r; asm("mov.b64 %0, {%1,%2};" : "=l"(r) : "f"(lo), "f"(hi)); return r;
}
__device__ __forceinline__ float2 unpack2(u64 v){
    float2 r; asm("mov.b64 {%0,%1}, %2;" : "=f"(r.x), "=f"(r.y) : "l"(v)); return r;
}

// ---------------- scratch ----------------
__device__ float g_h1[8*256*64*64];
__device__ float g_h2[8*256*32*32];
__device__ float g_r3[8*256*32*32];
__device__ float g_d1[8*256*32*32];
__device__ float g_d2[8*256*64*64];
__device__ float g_csq[512];
__device__ int   g_ids[8192];

// ---------------- conv1: 3->256, k4 s2 p1, 128->64, ReLU ----------------
// tile 16co x 16x16px, 4co x 4px per thread, ci pairs (0,1),(2,zero)
__global__ __launch_bounds__(256) void conv1_k(const float* __restrict__ x,
                                               const float* __restrict__ w,
                                               const float* __restrict__ bias){
    int b = blockIdx.z;
    int co0 = blockIdx.y * 16;
    int oy0 = (blockIdx.x >> 2) * 16, ox0 = (blockIdx.x & 3) * 16;
    __shared__ u64 s_w[2][16][16];
    __shared__ u64 s_in[2][34][35];
    int tid = threadIdx.x;
    int co_g = tid >> 6;
    int pg = tid & 63;
    int ly = pg >> 2, lx0 = (pg & 3) * 4;
    u64 acc[4][4] = {};
    const float* xb = x + (size_t)b*3*16384;
    int iyb = 2*oy0 - 1, ixb = 2*ox0 - 1;
    // weights
    for (int i = tid; i < 512; i += 256){
        int cp = i >> 8, tap = (i >> 4) & 15, col = i & 15;
        float a, bv;
        if (cp == 0){
            a  = w[(size_t)((co0+col)*3 + 0)*16 + tap];
            bv = w[(size_t)((co0+col)*3 + 1)*16 + tap];
        } else {
            a  = w[(size_t)((co0+col)*3 + 2)*16 + tap];
            bv = 0.f;
        }
        s_w[cp][tap][col] = pack2(a, bv);
    }
    // input
    for (int i = tid; i < 2312; i += 256){
        int cp = i / 1156, rem = i % 1156;
        int yy = rem / 34, xx = rem % 34;
        int iy = iyb + yy, ix = ixb + xx;
        float a = 0.f, bv = 0.f;
        if ((unsigned)iy < 128u && (unsigned)ix < 128u){
            if (cp == 0){
                a  = xb[(size_t)(0*128+iy)*128+ix];
                bv = xb[(size_t)(128+iy)*128+ix + 16384 - 16384];  // ci=1
                bv = xb[(size_t)(1*16384) + iy*128 + ix];
            } else {
                a  = xb[(size_t)(2*16384) + iy*128 + ix];
            }
        }
        s_in[cp][yy][xx] = pack2(a, bv);
    }
    __syncthreads();
    #pragma unroll
    for (int cp = 0; cp < 2; cp++){
        #pragma unroll
        for (int ky = 0; ky < 4; ky++){
            int ry = 2*ly + ky;
            #pragma unroll
            for (int kx = 0; kx < 4; kx++){
                int tap = ky*4 + kx;
                u64 wv[4];
                #pragma unroll
                for (int i = 0; i < 4; i++) wv[i] = s_w[cp][tap][co_g*4 + i];
                #pragma unroll
                for (int j = 0; j < 4; j++){
                    u64 iv = s_in[cp][ry][2*(lx0+j)+kx];
                    #pragma unroll
                    for (int i = 0; i < 4; i++) ffma2(acc[i][j], wv[i], iv);
                }
            }
        }
    }
    int oy = oy0 + ly;
    #pragma unroll
    for (int i = 0; i < 4; i++){
        int co = co0 + co_g*4 + i;
        float bb = bias[co];
        #pragma unroll
        for (int j = 0; j < 4; j++){
            int ox = ox0 + lx0 + j;
            float2 h = unpack2(acc[i][j]);
            g_h1[(size_t)((b*256+co)*64 + oy)*64 + ox] = fmaxf(h.x + h.y + bb, 0.f);
        }
    }
}

// ---------------- conv2: 256->256, k4 s2 p1, 64->32, ReLU ----------------
// tile 32co x 16x16px, 8co x 4px per thread, ci chunk 4 (2 pairs)
__global__ __launch_bounds__(256) void conv2_k(const float* __restrict__ w,
                                               const float* __restrict__ bias){
    int b = blockIdx.z;
    int co0 = blockIdx.y * 32;
    int oy0 = (blockIdx.x >> 1) * 16, ox0 = (blockIdx.x & 1) * 16;
    __shared__ u64 s_w[2][16][32];
    __shared__ u64 s_in[2][34][35];
    int tid = threadIdx.x;
    int co_g = tid >> 6;
    int pg = tid & 63;
    int ly = pg >> 2, lx0 = (pg & 3) * 4;
    u64 acc[8][4] = {};
    const float* inb = g_h1 + (size_t)b*256*4096;
    int iyb = 2*oy0 - 1, ixb = 2*ox0 - 1;
    for (int c0 = 0; c0 < 256; c0 += 4){
        for (int i = tid; i < 1024; i += 256){
            int cp = i >> 9, tap = (i >> 5) & 15, col = i & 31;
            size_t base = ((size_t)(co0+col)*256 + c0 + 2*cp)*16 + tap;
            s_w[cp][tap][col] = pack2(w[base], w[base+16]);
        }
        for (int i = tid; i < 2312; i += 256){
            int cp = i / 1156, rem = i % 1156;
            int yy = rem / 34, xx = rem % 34;
            int iy = iyb + yy, ix = ixb + xx;
            float a = 0.f, bv = 0.f;
            if ((unsigned)iy < 64u && (unsigned)ix < 64u){
                size_t base = ((size_t)(c0+2*cp)*64 + iy)*64 + ix;
                a = inb[base]; bv = inb[base + 4096];
            }
            s_in[cp][yy][xx] = pack2(a, bv);
        }
        __syncthreads();
        #pragma unroll
        for (int cp = 0; cp < 2; cp++){
            #pragma unroll
            for (int ky = 0; ky < 4; ky++){
                int ry = 2*ly + ky;
                #pragma unroll
                for (int kx = 0; kx < 4; kx++){
                    int tap = ky*4 + kx;
                    u64 wv[8];
                    #pragma unroll
                    for (int i = 0; i < 8; i++) wv[i] = s_w[cp][tap][co_g*8 + i];
                    #pragma unroll
                    for (int j = 0; j < 4; j++){
                        u64 iv = s_in[cp][ry][2*(lx0+j)+kx];
                        #pragma unroll
                        for (int i = 0; i < 8; i++) ffma2(acc[i][j], wv[i], iv);
                    }
                }
            }
        }
        __syncthreads();
    }
    int oy = oy0 + ly;
    #pragma unroll
    for (int i = 0; i < 8; i++){
        int co = co0 + co_g*8 + i;
        float bb = bias[co];
        #pragma unroll
        for (int j = 0; j < 4; j++){
            int ox = ox0 + lx0 + j;
            float2 h = unpack2(acc[i][j]);
            g_h2[(size_t)((b*256+co)*32 + oy)*32 + ox] = fmaxf(h.x + h.y + bb, 0.f);
        }
    }
}

// ---------------- conv3x3 pad1: relu(g_h2) -> g_r3 (+bias) ----------------
// tile 32co x 16x16px, 8co x 4px per thread, ci chunk 8 (4 pairs)
__global__ __launch_bounds__(256) void conv3_k(const float* __restrict__ w,
                                               const float* __restrict__ bias){
    int b = blockIdx.z;
    int co0 = blockIdx.y * 32;
    int oy0 = (blockIdx.x >> 1) * 16, ox0 = (blockIdx.x & 1) * 16;
    __shared__ u64 s_w[4][9][32];
    __shared__ u64 s_in[4][18][19];
    int tid = threadIdx.x;
    int co_g = tid >> 6;
    int pg = tid & 63;
    int ly = pg >> 2, lx0 = (pg & 3) * 4;
    u64 acc[8][4] = {};
    const float* inb = g_h2 + (size_t)b*256*1024;
    for (int c0 = 0; c0 < 256; c0 += 8){
        for (int i = tid; i < 1152; i += 256){
            int cp = i / 288, rem = i % 288;
            int tap = rem >> 5, col = rem & 31;
            size_t base = ((size_t)(co0+col)*256 + c0 + 2*cp)*9 + tap;
            s_w[cp][tap][col] = pack2(w[base], w[base+9]);
        }
        for (int i = tid; i < 1296; i += 256){
            int cp = i / 324, rem = i % 324;
            int yy = rem / 18, xx = rem % 18;
            int iy = oy0 - 1 + yy, ix = ox0 - 1 + xx;
            float a = 0.f, bv = 0.f;
            if ((unsigned)iy < 32u && (unsigned)ix < 32u){
                size_t base = ((size_t)(c0+2*cp)*32 + iy)*32 + ix;
                a = fmaxf(inb[base], 0.f); bv = fmaxf(inb[base + 1024], 0.f);
            }
            s_in[cp][yy][xx] = pack2(a, bv);
        }
        __syncthreads();
        #pragma unroll
        for (int cp = 0; cp < 4; cp++){
            #pragma unroll
            for (int ky = 0; ky < 3; ky++){
                int ry = ly + ky;
                #pragma unroll
                for (int kx = 0; kx < 3; kx++){
                    int tap = ky*3 + kx;
                    u64 wv[8];
                    #pragma unroll
                    for (int i = 0; i < 8; i++) wv[i] = s_w[cp][tap][co_g*8 + i];
                    #pragma unroll
                    for (int j = 0; j < 4; j++){
                        u64 iv = s_in[cp][ry][lx0 + j + kx];
                        #pragma unroll
                        for (int i = 0; i < 8; i++) ffma2(acc[i][j], wv[i], iv);
                    }
                }
            }
        }
        __syncthreads();
    }
    int oy = oy0 + ly;
    #pragma unroll
    for (int i = 0; i < 8; i++){
        int co = co0 + co_g*8 + i;
        float bb = bias[co];
        #pragma unroll
        for (int j = 0; j < 4; j++){
            int ox = ox0 + lx0 + j;
            float2 h = unpack2(acc[i][j]);
            g_r3[(size_t)((b*256+co)*32 + oy)*32 + ox] = h.x + h.y + bb;
        }
    }
}

// ---------------- conv1x1 GEMM ----------------
// tile 32co x 256px, 8co x 4px (px interleaved by 64), ci chunk 8 (4 pairs)
template<int CIN, bool RELU_IN, bool RELU_OUT, bool ADD_RES>
__global__ __launch_bounds__(256) void conv1x1_k(const float* __restrict__ in,
                                                 const float* __restrict__ w,
                                                 const float* __restrict__ bias,
                                                 const float* res, float* out){
    int b = blockIdx.z;
    int co0 = blockIdx.y * 32;
    int p0 = blockIdx.x * 256;
    int COUT = gridDim.y * 32;
    __shared__ u64 s_w[4][32];
    __shared__ u64 s_in[4][256];
    int tid = threadIdx.x;
    int co_g = tid >> 6;
    int px_g = tid & 63;
    u64 acc[8][4] = {};
    for (int c0 = 0; c0 < CIN; c0 += 8){
        if (tid < 128){
            int cp = tid >> 5, col = tid & 31;
            size_t base = (size_t)(co0+col)*CIN + c0 + 2*cp;
            s_w[cp][col] = pack2(w[base], w[base+1]);
        }
        for (int i = tid; i < 1024; i += 256){
            int cp = i >> 8, pp = i & 255;
            size_t base = (size_t)(b*CIN + c0 + 2*cp)*1024 + p0 + pp;
            float a = in[base], bv = in[base + 1024];
            if (RELU_IN){ a = fmaxf(a, 0.f); bv = fmaxf(bv, 0.f); }
            s_in[cp][pp] = pack2(a, bv);
        }
        __syncthreads();
        #pragma unroll
        for (int cp = 0; cp < 4; cp++){
            u64 wv[8];
            #pragma unroll
            for (int i = 0; i < 8; i++) wv[i] = s_w[cp][co_g*8 + i];
            #pragma unroll
            for (int j = 0; j < 4; j++){
                u64 iv = s_in[cp][px_g + 64*j];
                #pragma unroll
                for (int i = 0; i < 8; i++) ffma2(acc[i][j], wv[i], iv);
            }
        }
        __syncthreads();
    }
    #pragma unroll
    for (int i = 0; i < 8; i++){
        int co = co0 + co_g*8 + i;
        float bb = bias[co];
        #pragma unroll
        for (int j = 0; j < 4; j++){
            int p = p0 + px_g + 64*j;
            size_t idx = (size_t)(b*COUT + co)*1024 + p;
            float2 h = unpack2(acc[i][j]);
            float v = h.x + h.y + bb;
            if (ADD_RES) v += res[idx];
            if (RELU_OUT) v = fmaxf(v, 0.f);
            out[idx] = v;
        }
    }
}

// ---------------- VQ ----------------
__global__ void csq_k(const float* __restrict__ cb){
    int k = blockIdx.x*blockDim.x + threadIdx.x;
    if (k < 512){
        float s = 0.f;
        #pragma unroll
        for (int c = 0; c < 64; c++){ float v = cb[k*64+c]; s += v*v; }
        g_csq[k] = s;
    }
}

__global__ __launch_bounds__(256) void vq_k(const float* __restrict__ ze,
                                            const float* __restrict__ cb,
                                            float* __restrict__ ids_out){
    int warp = threadIdx.x >> 5, lane = threadIdx.x & 31;
    int n = blockIdx.x * 32 + lane;
    int b = n >> 10, p = n & 1023;
    const float* zb = ze + (size_t)b*65536 + p;
    u64 zp[32];
    float zz = 0.f;
    #pragma unroll
    for (int c2 = 0; c2 < 32; c2++){
        float a = zb[(size_t)(2*c2)*1024];
        float bv = zb[(size_t)(2*c2+1)*1024];
        zz += a*a + bv*bv;
        zp[c2] = pack2(a, bv);
    }
    float best = INFINITY; int bk = 0;
    int k0 = warp * 64;
    for (int kk = 0; kk < 64; kk++){
        int k = k0 + kk;
        const float2* cp2 = (const float2*)(cb + (size_t)k*64);
        u64 dot2 = 0;
        #pragma unroll
        for (int c2 = 0; c2 < 32; c2++){
            float2 cv = __ldg(&cp2[c2]);
            ffma2(dot2, zp[c2], pack2(cv.x, cv.y));
        }
        float2 dh = unpack2(dot2);
        float d = (zz - 2.0f*(dh.x + dh.y)) + g_csq[k];
        if (d < best){ best = d; bk = k; }
    }
    __shared__ float sv[8][32];
    __shared__ int   si[8][32];
    sv[warp][lane] = best; si[warp][lane] = bk;
    __syncthreads();
    if (warp == 0){
        float bv = sv[0][lane]; int bi = si[0][lane];
        #pragma unroll
        for (int w = 1; w < 8; w++){
            float v = sv[w][lane];
            if (v < bv){ bv = v; bi = si[w][lane]; }
        }
        g_ids[n] = bi;
        ids_out[n] = (float)bi;
    }
}

__global__ void ek_k(const float* __restrict__ cb, float* __restrict__ ek){
    int i = blockIdx.x*256 + threadIdx.x;
    if (i >= 8*64*1024) return;
    int b = i >> 16;
    int c = (i >> 10) & 63;
    int p = i & 1023;
    ek[i] = cb[(size_t)g_ids[(b<<10)|p]*64 + c];
}

// ---------------- t1: ConvTranspose 256->256, k4 s2 p1, 32->64, ReLU ----------------
// parity decomposition: each thread handles input coords (y, x..x+1) -> 2x4 outputs, 4 co.
// tile: input 16x16 (-> out 32x32) x 8 co.
__global__ __launch_bounds__(256) void t1_k(const float* __restrict__ w,
                                            const float* __restrict__ bias){
    int b = blockIdx.z;
    int co0 = blockIdx.y * 8;
    int y0 = (blockIdx.x >> 1) * 16, x0 = (blockIdx.x & 1) * 16;
    __shared__ u64 s_w[4][16][8];
    __shared__ u64 s_in[4][18][19];
    int tid = threadIdx.x;
    int co_g = tid >> 7;       // 0..1, 4 co each
    int s = tid & 127;
    int y_l = s >> 3;          // 0..15
    int x_l = (s & 7) * 2;     // 0,2,...,14
    u64 acc[4][8] = {};        // [co][py*4+px*2+u]
    const float* inb = g_d1 + (size_t)b*256*1024;
    for (int c0 = 0; c0 < 256; c0 += 8){
        for (int i = tid; i < 512; i += 256){
            int cp = i >> 7, tap = (i >> 3) & 15, col = i & 7;
            size_t base = ((size_t)(c0+2*cp)*256 + co0+col)*16 + tap;
            s_w[cp][tap][col] = pack2(w[base], w[base+4096]);
        }
        for (int i = tid; i < 1296; i += 256){
            int cp = i / 324, rem = i % 324;
            int yy = rem / 18, xx = rem % 18;
            int iy = y0 - 1 + yy, ix = x0 - 1 + xx;
            float a = 0.f, bv = 0.f;
            if ((unsigned)iy < 32u && (unsigned)ix < 32u){
                size_t base = ((size_t)(c0+2*cp)*32 + iy)*32 + ix;
                a = inb[base]; bv = inb[base + 1024];
            }
            s_in[cp][yy][xx] = pack2(a, bv);
        }
        __syncthreads();
        #pragma unroll
        for (int cp = 0; cp < 4; cp++){
            #pragma unroll
            for (int ky = 0; ky < 4; ky++){
                const int dy = 1 - ((ky+1) >> 1);
                const int py = (ky+1) & 1;
                int ryl = y_l + dy + 1;
                u64 riv[4];
                #pragma unroll
                for (int t = 0; t < 4; t++) riv[t] = s_in[cp][ryl][x_l + t];
                #pragma unroll
                for (int kx = 0; kx < 4; kx++){
                    const int dxv = 1 - ((kx+1) >> 1);
                    const int px = (kx+1) & 1;
                    int tap = ky*4 + kx;
                    u64 wv[4];
                    #pragma unroll
                    for (int i = 0; i < 4; i++) wv[i] = s_w[cp][tap][co_g*4 + i];
                    int o = py*4 + px*2;
                    #pragma unroll
                    for (int i = 0; i < 4; i++){
                        ffma2(acc[i][o],   wv[i], riv[dxv + 1]);
                        ffma2(acc[i][o+1], wv[i], riv[dxv + 2]);
                    }
                }
            }
        }
        __syncthreads();
    }
    int y = y0 + y_l, x = x0 + x_l;
    #pragma unroll
    for (int i = 0; i < 4; i++){
        int co = co0 + co_g*4 + i;
        float bb = bias[co];
        #pragma unroll
        for (int py = 0; py < 2; py++)
        #pragma unroll
        for (int px = 0; px < 2; px++)
        #pragma unroll
        for (int u = 0; u < 2; u++){
            float2 h = unpack2(acc[i][py*4 + px*2 + u]);
            int oy = 2*y + py, ox = 2*(x+u) + px;
            g_d2[(size_t)((b*256+co)*64 + oy)*64 + ox] = fmaxf(h.x + h.y + bb, 0.f);
        }
    }
}

// ---------------- t2: ConvTranspose 256->3, k4 s2 p1, 64->128, sigmoid ----------------
__global__ __launch_bounds__(256) void t2_k(const float* __restrict__ w,
                                            const float* __restrict__ bias,
                                            float* __restrict__ out){
    int b = blockIdx.y;
    int r = blockIdx.x;
    int tid = threadIdx.x;
    int sub = tid >> 7;
    int ox = tid & 127;
    int oy = 2*r + sub;
    __shared__ float s_w[32][3][16];
    __shared__ float s_in[32][3][64];
    float acc[3] = {0.f, 0.f, 0.f};
    const float* inb = g_d2 + (size_t)b*256*4096;
    for (int c0 = 0; c0 < 256; c0 += 32){
        for (int i = tid; i < 1536; i += 256){
            int ci = i / 48, rem = i % 48;
            int co = rem / 16, tap = rem % 16;
            s_w[ci][co][tap] = w[(size_t)((c0+ci)*3 + co)*16 + tap];
        }
        for (int i = tid; i < 6144; i += 256){
            int ci = i / 192, rem = i % 192;
            int ryl = rem / 64, ix = rem % 64;
            int iy = r - 1 + ryl;
            float v = 0.f;
            if ((unsigned)iy < 64u)
                v = inb[(size_t)((c0+ci)*64 + iy)*64 + ix];
            s_in[ci][ryl][ix] = v;
        }
        __syncthreads();
        int kyb = (oy + 1) & 1;
        int kxb = (ox + 1) & 1;
        #pragma unroll 4
        for (int ci = 0; ci < 32; ci++){
            #pragma unroll
            for (int kyi = 0; kyi < 2; kyi++){
                int ky = kyb + 2*kyi;
                int ryl = ((oy + 1 - ky) >> 1) - (r - 1);
                #pragma unroll
                for (int kxi = 0; kxi < 2; kxi++){
                    int kx = kxb + 2*kxi;
                    int ix = (ox + 1 - kx) >> 1;
                    if ((unsigned)ix < 64u){
                        float iv = s_in[ci][ryl][ix];
                        int tap = ky*4 + kx;
                        acc[0] = fmaf(s_w[ci][0][tap], iv, acc[0]);
                        acc[1] = fmaf(s_w[ci][1][tap], iv, acc[1]);
                        acc[2] = fmaf(s_w[ci][2][tap], iv, acc[2]);
                    }
                }
            }
        }
        __syncthreads();
    }
    #pragma unroll
    for (int co = 0; co < 3; co++){
        float v = acc[co] + bias[co];
        out[(size_t)((b*3+co)*128 + oy)*128 + ox] = 1.f/(1.f + expf(-v));
    }
}

// ---------------- launch ----------------
extern "C" void kernel_launch(void* const* d_in, const int* in_sizes, int n_in,
                              void* d_out, int out_size){
    const float* x        = (const float*)d_in[0];
    const float* c1_w     = (const float*)d_in[1];
    const float* c1_b     = (const float*)d_in[2];
    const float* c2_w     = (const float*)d_in[3];
    const float* c2_b     = (const float*)d_in[4];
    const float* r0_w3    = (const float*)d_in[5];
    const float* r0_b3    = (const float*)d_in[6];
    const float* r0_w1    = (const float*)d_in[7];
    const float* r0_b1    = (const float*)d_in[8];
    const float* r1_w3    = (const float*)d_in[9];
    const float* r1_b3    = (const float*)d_in[10];
    const float* r1_w1    = (const float*)d_in[11];
    const float* r1_b1    = (const float*)d_in[12];
    const float* to_z_w   = (const float*)d_in[13];
    const float* to_z_b   = (const float*)d_in[14];
    const float* codebook = (const float*)d_in[15];
    const float* from_z_w = (const float*)d_in[16];
    const float* from_z_b = (const float*)d_in[17];
    const float* t1_w     = (const float*)d_in[18];
    const float* t1_b     = (const float*)d_in[19];
    const float* t2_w     = (const float*)d_in[20];
    const float* t2_b     = (const float*)d_in[21];

    float* outf = (float*)d_out;
    float* ze   = outf + 393216;
    float* ek   = outf + 917504;
    float* idsf = outf + 1441792;

    float *p_h2 = 0, *p_r3 = 0, *p_d1 = 0;
    cudaGetSymbolAddress((void**)&p_h2, g_h2);
    cudaGetSymbolAddress((void**)&p_r3, g_r3);
    cudaGetSymbolAddress((void**)&p_d1, g_d1);

    conv1_k<<<dim3(16,16,8), 256>>>(x, c1_w, c1_b);
    conv2_k<<<dim3(4,8,8), 256>>>(c2_w, c2_b);
    conv3_k<<<dim3(4,8,8), 256>>>(r0_w3, r0_b3);
    conv1x1_k<256,true,false,true><<<dim3(4,8,8), 256>>>(p_r3, r0_w1, r0_b1, p_h2, p_h2);
    conv3_k<<<dim3(4,8,8), 256>>>(r1_w3, r1_b3);
    conv1x1_k<256,true,false,true><<<dim3(4,8,8), 256>>>(p_r3, r1_w1, r1_b1, p_h2, p_h2);
    conv1x1_k<256,false,false,false><<<dim3(4,2,8), 256>>>(p_h2, to_z_w, to_z_b, nullptr, ze);
    csq_k<<<2,256>>>(codebook);
    vq_k<<<256,256>>>(ze, codebook, idsf);
    ek_k<<<2048,256>>>(codebook, ek);
    conv1x1_k<64,false,true,false><<<dim3(4,8,8), 256>>>(ek, from_z_w, from_z_b, nullptr, p_d1);
    t1_k<<<dim3(4,32,8), 256>>>(t1_w, t1_b);
    t2_k<<<dim3(64,8), 256>>>(t2_w, t2_b, outf);
}